// round 3
// baseline (speedup 1.0000x reference)
#include <cuda_runtime.h>

#define FULL 0xffffffffu

constexpr int P = 4096, F = 64, HG = 64, C = 64, T = 32, E = 65536, HOUT = 12;
constexpr float EPS = 1e-5f;

// ---- scratch (static device globals; no allocation at runtime) ----
__device__ float g_Xt[T * P * F];     // X transposed: [t][p][f]
__device__ float g_hl[T * P * HG];    // x @ Wl
__device__ float g_hr[T * P * HG];    // x @ Wr
__device__ int   g_deg[T * P];
__device__ int   g_offs[T * P];
__device__ int   g_cur[T * P];
__device__ int   g_elist[T * E];      // src node ids grouped by dst (CSR payload)
__device__ float g_Xhat[T * P * HG];  // relu(GAT out)
__device__ float g_yn[P * T * C];     // LayerNormed y, [p][t][c]

__device__ __forceinline__ float leaky(float x) { return x > 0.f ? x : 0.2f * x; }

__device__ __forceinline__ float warp_sum(float v) {
    v += __shfl_xor_sync(FULL, v, 16);
    v += __shfl_xor_sync(FULL, v, 8);
    v += __shfl_xor_sync(FULL, v, 4);
    v += __shfl_xor_sync(FULL, v, 2);
    v += __shfl_xor_sync(FULL, v, 1);
    return v;
}

// ---- K0: transpose X[1,P,F,T] -> Xt[t][p][f] ----
__global__ void k_transpose(const float* __restrict__ X) {
    __shared__ float sm[64 * 33];
    int p = blockIdx.x;
    const float* xp = X + (size_t)p * (F * T);
    for (int idx = threadIdx.x; idx < F * T; idx += blockDim.x) {
        int f = idx >> 5, t = idx & 31;           // [f][t], t inner
        sm[f * 33 + t] = xp[idx];
    }
    __syncthreads();
    for (int idx = threadIdx.x; idx < F * T; idx += blockDim.x) {
        int t = idx >> 6, f = idx & 63;           // write [t][f], f inner
        g_Xt[((size_t)t * P + p) * 64 + f] = sm[f * 33 + t];
    }
}

// ---- K1: hl = x@Wl, hr = x@Wr  (warp per (t,p)) ----
__global__ void k_proj(const float* __restrict__ Wl, const float* __restrict__ Wr) {
    __shared__ float sWl[4096], sWr[4096];
    for (int i = threadIdx.x; i < 4096; i += blockDim.x) { sWl[i] = Wl[i]; sWr[i] = Wr[i]; }
    __syncthreads();
    int warp = blockIdx.x * (blockDim.x >> 5) + (threadIdx.x >> 5);
    int lane = threadIdx.x & 31;
    const float* x = g_Xt + (size_t)warp * 64;
    float x0 = x[lane], x1 = x[lane + 32];
    float l0 = 0.f, l1 = 0.f, r0 = 0.f, r1 = 0.f;
#pragma unroll
    for (int f = 0; f < 32; f++) {
        float b = __shfl_sync(FULL, x0, f);
        l0 += b * sWl[f * 64 + lane];      l1 += b * sWl[f * 64 + lane + 32];
        r0 += b * sWr[f * 64 + lane];      r1 += b * sWr[f * 64 + lane + 32];
    }
#pragma unroll
    for (int f = 0; f < 32; f++) {
        float b = __shfl_sync(FULL, x1, f);
        l0 += b * sWl[(f + 32) * 64 + lane];      l1 += b * sWl[(f + 32) * 64 + lane + 32];
        r0 += b * sWr[(f + 32) * 64 + lane];      r1 += b * sWr[(f + 32) * 64 + lane + 32];
    }
    float* hl = g_hl + (size_t)warp * 64;
    float* hr = g_hr + (size_t)warp * 64;
    hl[lane] = l0; hl[lane + 32] = l1;
    hr[lane] = r0; hr[lane + 32] = r1;
}

// ---- K2: zero degree / cursor (must reset every launch: graph replays) ----
__global__ void k_zero() {
    int i = blockIdx.x * blockDim.x + threadIdx.x;
    if (i < T * P) { g_deg[i] = 0; g_cur[i] = 0; }
}

// ---- K3: count in-degree per (t,dst) ----
__global__ void k_count(const int* __restrict__ ei) {
    int gid = blockIdx.x * blockDim.x + threadIdx.x;  // T*E threads
    int t = gid >> 16, e = gid & (E - 1);
    int dst = ei[(size_t)t * 2 * E + E + e];
    atomicAdd(&g_deg[t * P + dst], 1);
}

// ---- K4: per-t exclusive scan of degrees (block of 1024, 4 elems/thread) ----
__global__ void k_scan() {
    __shared__ int sm[1024];
    int t = blockIdx.x, tid = threadIdx.x;
    int base = t * P + tid * 4;
    int d0 = g_deg[base], d1 = g_deg[base + 1], d2 = g_deg[base + 2], d3 = g_deg[base + 3];
    sm[tid] = d0 + d1 + d2 + d3;
    __syncthreads();
    for (int off = 1; off < 1024; off <<= 1) {
        int v = (tid >= off) ? sm[tid - off] : 0;
        __syncthreads();
        sm[tid] += v;
        __syncthreads();
    }
    int excl = tid ? sm[tid - 1] : 0;
    g_offs[base]     = excl;
    g_offs[base + 1] = excl + d0;
    g_offs[base + 2] = excl + d0 + d1;
    g_offs[base + 3] = excl + d0 + d1 + d2;
}

// ---- K5: place src ids into CSR buckets ----
__global__ void k_place(const int* __restrict__ ei) {
    int gid = blockIdx.x * blockDim.x + threadIdx.x;
    int t = gid >> 16, e = gid & (E - 1);
    int src = ei[(size_t)t * 2 * E + e];
    int dst = ei[(size_t)t * 2 * E + E + e];
    int pos = atomicAdd(&g_cur[t * P + dst], 1);
    g_elist[(size_t)t * E + g_offs[t * P + dst] + pos] = src;
}

// ---- K6: GAT with online segment-softmax (warp per (t,dst)) ----
__global__ void k_gat(const float* __restrict__ att, const float* __restrict__ gat_b) {
    int warp = blockIdx.x * (blockDim.x >> 5) + (threadIdx.x >> 5);
    int lane = threadIdx.x & 31;
    int t = warp >> 12;               // P = 4096
    float hr0 = g_hr[(size_t)warp * 64 + lane];
    float hr1 = g_hr[(size_t)warp * 64 + lane + 32];
    float at0 = __ldg(&att[lane]), at1 = __ldg(&att[lane + 32]);
    int start = g_offs[warp], deg = g_deg[warp];
    float m = -1e30f, s = 0.f, acc0 = 0.f, acc1 = 0.f;
    const float* hlbase = g_hl + (size_t)t * P * 64;
    const int* el = g_elist + (size_t)t * E + start;
    for (int k = 0; k < deg; k += 32) {
        int srcs = (k + lane < deg) ? el[k + lane] : 0;
        int n = min(32, deg - k);
        for (int j = 0; j < n; j++) {
            int sj = __shfl_sync(FULL, srcs, j);
            const float* hp = hlbase + (size_t)sj * 64;
            float v0 = hp[lane], v1 = hp[lane + 32];
            float sc = leaky(v0 + hr0) * at0 + leaky(v1 + hr1) * at1;
            sc = warp_sum(sc);
            float mn = fmaxf(m, sc);
            float cor = __expf(m - mn);
            float w = __expf(sc - mn);
            s = s * cor + w;
            acc0 = acc0 * cor + w * v0;
            acc1 = acc1 * cor + w * v1;
            m = mn;
        }
    }
    float inv = (deg > 0) ? 1.f / s : 0.f;
    float o0 = fmaxf(acc0 * inv + __ldg(&gat_b[lane]), 0.f);
    float o1 = fmaxf(acc1 * inv + __ldg(&gat_b[lane + 32]), 0.f);
    g_Xhat[(size_t)warp * 64 + lane] = o0;
    g_Xhat[(size_t)warp * 64 + lane + 32] = o1;
}

// ---- K7: time conv + residual conv + relu + LayerNorm (warp per (t,p)) ----
__global__ void k_epi(const float* __restrict__ Wt, const float* __restrict__ bt,
                      const float* __restrict__ Wr_, const float* __restrict__ br,
                      const float* __restrict__ lng, const float* __restrict__ lnb) {
    __shared__ float sWt[4096], sWr[4096];   // transposed to [h][c] for conflict-free reads
    for (int idx = threadIdx.x; idx < 4096; idx += blockDim.x) {
        int c = idx >> 6, h = idx & 63;
        sWt[h * 64 + c] = Wt[idx];           // W_time is (C, HG) row-major
        sWr[h * 64 + c] = Wr_[idx];          // W_res  is (C, F)  row-major
    }
    __syncthreads();
    int warp = blockIdx.x * (blockDim.x >> 5) + (threadIdx.x >> 5);
    int lane = threadIdx.x & 31;
    int t = warp >> 12, p = warp & (P - 1);
    float xh0 = g_Xhat[(size_t)warp * 64 + lane], xh1 = g_Xhat[(size_t)warp * 64 + lane + 32];
    float xf0 = g_Xt[(size_t)warp * 64 + lane],   xf1 = g_Xt[(size_t)warp * 64 + lane + 32];
    float th0 = 0.f, th1 = 0.f, rs0 = 0.f, rs1 = 0.f;
#pragma unroll
    for (int k = 0; k < 32; k++) {
        float bh = __shfl_sync(FULL, xh0, k);
        float bf = __shfl_sync(FULL, xf0, k);
        th0 += bh * sWt[k * 64 + lane]; th1 += bh * sWt[k * 64 + lane + 32];
        rs0 += bf * sWr[k * 64 + lane]; rs1 += bf * sWr[k * 64 + lane + 32];
    }
#pragma unroll
    for (int k = 0; k < 32; k++) {
        float bh = __shfl_sync(FULL, xh1, k);
        float bf = __shfl_sync(FULL, xf1, k);
        th0 += bh * sWt[(k + 32) * 64 + lane]; th1 += bh * sWt[(k + 32) * 64 + lane + 32];
        rs0 += bf * sWr[(k + 32) * 64 + lane]; rs1 += bf * sWr[(k + 32) * 64 + lane + 32];
    }
    float y0 = fmaxf(th0 + __ldg(&bt[lane]) + rs0 + __ldg(&br[lane]), 0.f);
    float y1 = fmaxf(th1 + __ldg(&bt[lane + 32]) + rs1 + __ldg(&br[lane + 32]), 0.f);
    float mu = warp_sum(y0 + y1) * (1.f / 64.f);
    float d0 = y0 - mu, d1 = y1 - mu;
    float var = warp_sum(d0 * d0 + d1 * d1) * (1.f / 64.f);
    float r = rsqrtf(var + EPS);
    float yn0 = d0 * r * __ldg(&lng[lane]) + __ldg(&lnb[lane]);
    float yn1 = d1 * r * __ldg(&lng[lane + 32]) + __ldg(&lnb[lane + 32]);
    g_yn[(size_t)p * (T * C) + t * 64 + lane] = yn0;
    g_yn[(size_t)p * (T * C) + t * 64 + lane + 32] = yn1;
}

// ---- K8: final contraction out[p][o] = sum_{t,c} yn[p][t][c] * Wf[o][t][c] ----
__global__ void k_final(const float* __restrict__ Wf, const float* __restrict__ bf,
                        float* __restrict__ out) {
    int warp = blockIdx.x * (blockDim.x >> 5) + (threadIdx.x >> 5);
    int lane = threadIdx.x & 31;
    int p = warp;
    const float* y = g_yn + (size_t)p * (T * C);
    float acc[HOUT];
#pragma unroll
    for (int o = 0; o < HOUT; o++) acc[o] = 0.f;
    for (int idx = lane; idx < T * C; idx += 32) {
        float yv = y[idx];
#pragma unroll
        for (int o = 0; o < HOUT; o++) acc[o] += yv * __ldg(&Wf[o * (T * C) + idx]);
    }
    float myval = 0.f;
#pragma unroll
    for (int o = 0; o < HOUT; o++) {
        float v = warp_sum(acc[o]);
        if (lane == o) myval = v;
    }
    if (lane < HOUT) out[p * HOUT + lane] = myval + __ldg(&bf[lane]);
}

extern "C" void kernel_launch(void* const* d_in, const int* in_sizes, int n_in,
                              void* d_out, int out_size) {
    const float* X       = (const float*)d_in[0];
    const int*   ei      = (const int*)  d_in[1];
    const float* Wl      = (const float*)d_in[2];
    const float* Wr      = (const float*)d_in[3];
    const float* att     = (const float*)d_in[4];
    const float* gat_b   = (const float*)d_in[5];
    const float* W_time  = (const float*)d_in[6];
    const float* b_time  = (const float*)d_in[7];
    const float* W_res   = (const float*)d_in[8];
    const float* b_res   = (const float*)d_in[9];
    const float* ln_g    = (const float*)d_in[10];
    const float* ln_b    = (const float*)d_in[11];
    const float* W_final = (const float*)d_in[12];
    const float* b_final = (const float*)d_in[13];
    float* out = (float*)d_out;

    k_transpose<<<P, 256>>>(X);
    k_proj<<<T * P / 8, 256>>>(Wl, Wr);
    k_zero<<<(T * P) / 256, 256>>>();
    k_count<<<T * E / 256, 256>>>(ei);
    k_scan<<<T, 1024>>>();
    k_place<<<T * E / 256, 256>>>(ei);
    k_gat<<<T * P / 8, 256>>>(att, gat_b);
    k_epi<<<T * P / 8, 256>>>(W_time, b_time, W_res, b_res, ln_g, ln_b);
    k_final<<<P / 8, 256>>>(W_final, b_final, out);
}

// round 4
// speedup vs baseline: 1.8873x; 1.8873x over previous
#include <cuda_runtime.h>

#define FULL 0xffffffffu

constexpr int P = 4096, F = 64, HG = 64, C = 64, T = 32, E = 65536, HOUT = 12;
constexpr float EPS = 1e-5f;
constexpr int MAXD = 256;   // per-segment score buffer cap (mean deg=16, Poisson tail ~0)

// ---- scratch (static device globals; no allocation at runtime) ----
__device__ float g_Xt[T * P * F];     // X transposed: [t][p][f]
__device__ float g_hl[T * P * HG];    // x @ Wl
__device__ float g_hr[T * P * HG];    // x @ Wr
__device__ int   g_deg[T * P];
__device__ int   g_offs[T * P];
__device__ int   g_cur[T * P];
__device__ int   g_elist[T * E];      // src node ids grouped by dst (CSR payload)
__device__ float g_Xhat[T * P * HG];  // relu(GAT out)
__device__ float g_yn[P * T * C];     // LayerNormed y, [p][t][c]

__device__ __forceinline__ float leaky(float x) { return x > 0.f ? x : 0.2f * x; }

__device__ __forceinline__ float warp_sum(float v) {
    v += __shfl_xor_sync(FULL, v, 16);
    v += __shfl_xor_sync(FULL, v, 8);
    v += __shfl_xor_sync(FULL, v, 4);
    v += __shfl_xor_sync(FULL, v, 2);
    v += __shfl_xor_sync(FULL, v, 1);
    return v;
}

__device__ __forceinline__ float warp_max(float v) {
    v = fmaxf(v, __shfl_xor_sync(FULL, v, 16));
    v = fmaxf(v, __shfl_xor_sync(FULL, v, 8));
    v = fmaxf(v, __shfl_xor_sync(FULL, v, 4));
    v = fmaxf(v, __shfl_xor_sync(FULL, v, 2));
    v = fmaxf(v, __shfl_xor_sync(FULL, v, 1));
    return v;
}

// ---- K0: transpose X[1,P,F,T] -> Xt[t][p][f] ----
__global__ void k_transpose(const float* __restrict__ X) {
    __shared__ float sm[64 * 33];
    int p = blockIdx.x;
    const float* xp = X + (size_t)p * (F * T);
    for (int idx = threadIdx.x; idx < F * T; idx += blockDim.x) {
        int f = idx >> 5, t = idx & 31;           // [f][t], t inner
        sm[f * 33 + t] = xp[idx];
    }
    __syncthreads();
    for (int idx = threadIdx.x; idx < F * T; idx += blockDim.x) {
        int t = idx >> 6, f = idx & 63;           // write [t][f], f inner
        g_Xt[((size_t)t * P + p) * 64 + f] = sm[f * 33 + t];
    }
}

// ---- K1: hl = x@Wl, hr = x@Wr  (warp per 4 rows: weight LDS amortized 4x) ----
__global__ void __launch_bounds__(256) k_proj(const float* __restrict__ Wl,
                                              const float* __restrict__ Wr) {
    __shared__ float sWl[4096], sWr[4096];
    for (int i = threadIdx.x; i < 4096; i += blockDim.x) { sWl[i] = Wl[i]; sWr[i] = Wr[i]; }
    __syncthreads();
    int w = blockIdx.x * 8 + (threadIdx.x >> 5);
    int lane = threadIdx.x & 31;
    int row0 = w * 4;
    float x0[4], x1[4];
#pragma unroll
    for (int r = 0; r < 4; r++) {
        const float* x = g_Xt + (size_t)(row0 + r) * 64;
        x0[r] = x[lane]; x1[r] = x[lane + 32];
    }
    float al0[4] = {0,0,0,0}, al1[4] = {0,0,0,0}, ar0[4] = {0,0,0,0}, ar1[4] = {0,0,0,0};
#pragma unroll 8
    for (int k = 0; k < 32; k++) {
        float wl0 = sWl[k * 64 + lane], wl1 = sWl[k * 64 + lane + 32];
        float wr0 = sWr[k * 64 + lane], wr1 = sWr[k * 64 + lane + 32];
#pragma unroll
        for (int r = 0; r < 4; r++) {
            float b = __shfl_sync(FULL, x0[r], k);
            al0[r] += b * wl0; al1[r] += b * wl1;
            ar0[r] += b * wr0; ar1[r] += b * wr1;
        }
    }
#pragma unroll 8
    for (int k = 0; k < 32; k++) {
        float wl0 = sWl[(k + 32) * 64 + lane], wl1 = sWl[(k + 32) * 64 + lane + 32];
        float wr0 = sWr[(k + 32) * 64 + lane], wr1 = sWr[(k + 32) * 64 + lane + 32];
#pragma unroll
        for (int r = 0; r < 4; r++) {
            float b = __shfl_sync(FULL, x1[r], k);
            al0[r] += b * wl0; al1[r] += b * wl1;
            ar0[r] += b * wr0; ar1[r] += b * wr1;
        }
    }
#pragma unroll
    for (int r = 0; r < 4; r++) {
        float* hl = g_hl + (size_t)(row0 + r) * 64;
        float* hr = g_hr + (size_t)(row0 + r) * 64;
        hl[lane] = al0[r]; hl[lane + 32] = al1[r];
        hr[lane] = ar0[r]; hr[lane + 32] = ar1[r];
    }
}

// ---- K2: zero degree / cursor (graph replays: must reset each launch) ----
__global__ void k_zero() {
    int i = blockIdx.x * blockDim.x + threadIdx.x;
    if (i < T * P) { g_deg[i] = 0; g_cur[i] = 0; }
}

// ---- K3: count in-degree, per-block smem histogram (8 blocks per t) ----
__global__ void __launch_bounds__(1024) k_count(const int* __restrict__ ei) {
    __shared__ int h[P];
    int t = blockIdx.x >> 3, chunk = blockIdx.x & 7;
    for (int i = threadIdx.x; i < P; i += 1024) h[i] = 0;
    __syncthreads();
    const int* dstp = ei + (size_t)t * 2 * E + E + chunk * 8192;
#pragma unroll
    for (int it = 0; it < 8; it++) {
        int dst = dstp[it * 1024 + threadIdx.x];
        atomicAdd(&h[dst], 1);
    }
    __syncthreads();
    for (int i = threadIdx.x; i < P; i += 1024)
        if (h[i]) atomicAdd(&g_deg[t * P + i], h[i]);
}

// ---- K4: per-t exclusive scan of degrees ----
__global__ void k_scan() {
    __shared__ int sm[1024];
    int t = blockIdx.x, tid = threadIdx.x;
    int base = t * P + tid * 4;
    int d0 = g_deg[base], d1 = g_deg[base + 1], d2 = g_deg[base + 2], d3 = g_deg[base + 3];
    sm[tid] = d0 + d1 + d2 + d3;
    __syncthreads();
    for (int off = 1; off < 1024; off <<= 1) {
        int v = (tid >= off) ? sm[tid - off] : 0;
        __syncthreads();
        sm[tid] += v;
        __syncthreads();
    }
    int excl = tid ? sm[tid - 1] : 0;
    g_offs[base]     = excl;
    g_offs[base + 1] = excl + d0;
    g_offs[base + 2] = excl + d0 + d1;
    g_offs[base + 3] = excl + d0 + d1 + d2;
}

// ---- K5: place src ids into CSR buckets ----
__global__ void k_place(const int* __restrict__ ei) {
    int gid = blockIdx.x * blockDim.x + threadIdx.x;
    int t = gid >> 16, e = gid & (E - 1);
    int src = ei[(size_t)t * 2 * E + e];
    int dst = ei[(size_t)t * 2 * E + E + e];
    int pos = atomicAdd(&g_cur[t * P + dst], 1);
    g_elist[(size_t)t * E + g_offs[t * P + dst] + pos] = src;
}

// ---- K6: GAT, two-sweep softmax (no per-edge serial chain) ----
__global__ void __launch_bounds__(256) k_gat(const float* __restrict__ att,
                                             const float* __restrict__ gat_b) {
    __shared__ float ssc[8][MAXD];
    int wIdx = threadIdx.x >> 5;
    int lane = threadIdx.x & 31;
    int warp = blockIdx.x * 8 + wIdx;
    int t = warp >> 12;               // P = 4096
    float hr0 = g_hr[(size_t)warp * 64 + lane];
    float hr1 = g_hr[(size_t)warp * 64 + lane + 32];
    float at0 = __ldg(&att[lane]), at1 = __ldg(&att[lane + 32]);
    int start = g_offs[warp], deg = g_deg[warp];
    const float* hlbase = g_hl + (size_t)t * P * 64;
    const int* el = g_elist + (size_t)t * E + start;
    float acc0 = 0.f, acc1 = 0.f, inv;

    if (deg <= MAXD) {
        // sweep 1: all scores (edges independent -> latency overlaps)
        for (int k = 0; k < deg; k += 32) {
            int srcs = (k + lane < deg) ? el[k + lane] : 0;
            int n = min(32, deg - k);
            for (int j = 0; j < n; j++) {
                int sj = __shfl_sync(FULL, srcs, j);
                const float* hp = hlbase + (size_t)sj * 64;
                float sc = leaky(hp[lane] + hr0) * at0 + leaky(hp[lane + 32] + hr1) * at1;
                sc = warp_sum(sc);
                if (lane == 0) ssc[wIdx][k + j] = sc;
            }
        }
        __syncwarp();
        float mx = -1e30f;
        for (int i = lane; i < deg; i += 32) mx = fmaxf(mx, ssc[wIdx][i]);
        mx = warp_max(mx);
        float s = 0.f;
        for (int i = lane; i < deg; i += 32) {
            float e = __expf(ssc[wIdx][i] - mx);
            ssc[wIdx][i] = e;
            s += e;
        }
        s = warp_sum(s);
        __syncwarp();
        // sweep 2: pure weighted accumulation (L1-hot re-gather)
        for (int k = 0; k < deg; k += 32) {
            int srcs = (k + lane < deg) ? el[k + lane] : 0;
            int n = min(32, deg - k);
            for (int j = 0; j < n; j++) {
                int sj = __shfl_sync(FULL, srcs, j);
                float wgt = ssc[wIdx][k + j];   // same-addr LDS broadcast
                const float* hp = hlbase + (size_t)sj * 64;
                acc0 += wgt * hp[lane];
                acc1 += wgt * hp[lane + 32];
            }
        }
        inv = (deg > 0) ? 1.f / s : 0.f;
    } else {
        // fallback: online softmax (never taken for this distribution, kept for safety)
        float m = -1e30f, s = 0.f;
        for (int k = 0; k < deg; k += 32) {
            int srcs = (k + lane < deg) ? el[k + lane] : 0;
            int n = min(32, deg - k);
            for (int j = 0; j < n; j++) {
                int sj = __shfl_sync(FULL, srcs, j);
                const float* hp = hlbase + (size_t)sj * 64;
                float v0 = hp[lane], v1 = hp[lane + 32];
                float sc = leaky(v0 + hr0) * at0 + leaky(v1 + hr1) * at1;
                sc = warp_sum(sc);
                float mn = fmaxf(m, sc);
                float cor = __expf(m - mn);
                float wv = __expf(sc - mn);
                s = s * cor + wv;
                acc0 = acc0 * cor + wv * v0;
                acc1 = acc1 * cor + wv * v1;
                m = mn;
            }
        }
        inv = (deg > 0) ? 1.f / s : 0.f;
    }
    float o0 = fmaxf(acc0 * inv + __ldg(&gat_b[lane]), 0.f);
    float o1 = fmaxf(acc1 * inv + __ldg(&gat_b[lane + 32]), 0.f);
    g_Xhat[(size_t)warp * 64 + lane] = o0;
    g_Xhat[(size_t)warp * 64 + lane + 32] = o1;
}

// ---- K7: time conv + residual conv + relu + LayerNorm (warp per 4 rows) ----
__global__ void __launch_bounds__(256) k_epi(const float* __restrict__ Wt, const float* __restrict__ bt,
                                             const float* __restrict__ Wr_, const float* __restrict__ br,
                                             const float* __restrict__ lng, const float* __restrict__ lnb) {
    __shared__ float sWt[4096], sWr[4096];   // transposed to [h][c]
    for (int idx = threadIdx.x; idx < 4096; idx += blockDim.x) {
        int c = idx >> 6, h = idx & 63;
        sWt[h * 64 + c] = Wt[idx];           // W_time is (C, HG) row-major
        sWr[h * 64 + c] = Wr_[idx];          // W_res  is (C, F)  row-major
    }
    __syncthreads();
    int w = blockIdx.x * 8 + (threadIdx.x >> 5);
    int lane = threadIdx.x & 31;
    int row0 = w * 4;
    int t = row0 >> 12;
    float xh0[4], xh1[4], xf0[4], xf1[4];
#pragma unroll
    for (int r = 0; r < 4; r++) {
        size_t base = (size_t)(row0 + r) * 64;
        xh0[r] = g_Xhat[base + lane]; xh1[r] = g_Xhat[base + lane + 32];
        xf0[r] = g_Xt[base + lane];   xf1[r] = g_Xt[base + lane + 32];
    }
    float th0[4] = {0,0,0,0}, th1[4] = {0,0,0,0}, rs0[4] = {0,0,0,0}, rs1[4] = {0,0,0,0};
#pragma unroll 8
    for (int k = 0; k < 32; k++) {
        float wt0 = sWt[k * 64 + lane], wt1 = sWt[k * 64 + lane + 32];
        float wr0 = sWr[k * 64 + lane], wr1 = sWr[k * 64 + lane + 32];
#pragma unroll
        for (int r = 0; r < 4; r++) {
            float bh = __shfl_sync(FULL, xh0[r], k);
            float bf = __shfl_sync(FULL, xf0[r], k);
            th0[r] += bh * wt0; th1[r] += bh * wt1;
            rs0[r] += bf * wr0; rs1[r] += bf * wr1;
        }
    }
#pragma unroll 8
    for (int k = 0; k < 32; k++) {
        float wt0 = sWt[(k + 32) * 64 + lane], wt1 = sWt[(k + 32) * 64 + lane + 32];
        float wr0 = sWr[(k + 32) * 64 + lane], wr1 = sWr[(k + 32) * 64 + lane + 32];
#pragma unroll
        for (int r = 0; r < 4; r++) {
            float bh = __shfl_sync(FULL, xh1[r], k);
            float bf = __shfl_sync(FULL, xf1[r], k);
            th0[r] += bh * wt0; th1[r] += bh * wt1;
            rs0[r] += bf * wr0; rs1[r] += bf * wr1;
        }
    }
    float bt0 = __ldg(&bt[lane]) + __ldg(&br[lane]);
    float bt1 = __ldg(&bt[lane + 32]) + __ldg(&br[lane + 32]);
    float g0 = __ldg(&lng[lane]), g1 = __ldg(&lng[lane + 32]);
    float lb0 = __ldg(&lnb[lane]), lb1 = __ldg(&lnb[lane + 32]);
#pragma unroll
    for (int r = 0; r < 4; r++) {
        float y0 = fmaxf(th0[r] + rs0[r] + bt0, 0.f);
        float y1 = fmaxf(th1[r] + rs1[r] + bt1, 0.f);
        float mu = warp_sum(y0 + y1) * (1.f / 64.f);
        float d0 = y0 - mu, d1 = y1 - mu;
        float var = warp_sum(d0 * d0 + d1 * d1) * (1.f / 64.f);
        float rq = rsqrtf(var + EPS);
        int p = (row0 + r) & (P - 1);
        float* yp = g_yn + (size_t)p * (T * C) + t * 64;
        yp[lane]      = d0 * rq * g0 + lb0;
        yp[lane + 32] = d1 * rq * g1 + lb1;
    }
}

// ---- K8: final contraction out[p][o] = sum_{t,c} yn[p][t][c] * Wf[o][t][c] ----
__global__ void k_final(const float* __restrict__ Wf, const float* __restrict__ bf,
                        float* __restrict__ out) {
    int warp = blockIdx.x * (blockDim.x >> 5) + (threadIdx.x >> 5);
    int lane = threadIdx.x & 31;
    int p = warp;
    const float* y = g_yn + (size_t)p * (T * C);
    float acc[HOUT];
#pragma unroll
    for (int o = 0; o < HOUT; o++) acc[o] = 0.f;
    for (int idx = lane; idx < T * C; idx += 32) {
        float yv = y[idx];
#pragma unroll
        for (int o = 0; o < HOUT; o++) acc[o] += yv * __ldg(&Wf[o * (T * C) + idx]);
    }
    float myval = 0.f;
#pragma unroll
    for (int o = 0; o < HOUT; o++) {
        float v = warp_sum(acc[o]);
        if (lane == o) myval = v;
    }
    if (lane < HOUT) out[p * HOUT + lane] = myval + __ldg(&bf[lane]);
}

extern "C" void kernel_launch(void* const* d_in, const int* in_sizes, int n_in,
                              void* d_out, int out_size) {
    const float* X       = (const float*)d_in[0];
    const int*   ei      = (const int*)  d_in[1];
    const float* Wl      = (const float*)d_in[2];
    const float* Wr      = (const float*)d_in[3];
    const float* att     = (const float*)d_in[4];
    const float* gat_b   = (const float*)d_in[5];
    const float* W_time  = (const float*)d_in[6];
    const float* b_time  = (const float*)d_in[7];
    const float* W_res   = (const float*)d_in[8];
    const float* b_res   = (const float*)d_in[9];
    const float* ln_g    = (const float*)d_in[10];
    const float* ln_b    = (const float*)d_in[11];
    const float* W_final = (const float*)d_in[12];
    const float* b_final = (const float*)d_in[13];
    float* out = (float*)d_out;

    k_transpose<<<P, 256>>>(X);
    k_proj<<<T * P / 32, 256>>>(Wl, Wr);
    k_zero<<<(T * P) / 256, 256>>>();
    k_count<<<256, 1024>>>(ei);
    k_scan<<<T, 1024>>>();
    k_place<<<T * E / 256, 256>>>(ei);
    k_gat<<<T * P / 8, 256>>>(att, gat_b);
    k_epi<<<T * P / 32, 256>>>(W_time, b_time, W_res, b_res, ln_g, ln_b);
    k_final<<<P / 8, 256>>>(W_final, b_final, out);
}